// round 2
// baseline (speedup 1.0000x reference)
#include <cuda_runtime.h>
#include <cuda_bf16.h>
#include <math.h>

// Problem constants (fixed by the dataset)
#define B_  8
#define S_  8192
#define K_  512
#define DEPTH_ 2
#define BS_ (B_ * S_)               // 65536
#define BASE_ (K_ * K_)             // 262144
#define NROWS_ (DEPTH_ * BS_)       // 131072 softmax rows of 512

// ---------------- global accumulators (no device allocs allowed) -------------
__device__ double        g_ce_sum;
__device__ double        g_sp_sum;
__device__ unsigned int  g_valid_cnt;
__device__ unsigned int  g_sp_cnt;

__global__ void init_accum_kernel() {
    g_ce_sum = 0.0;
    g_sp_sum = 0.0;
    g_valid_cnt = 0u;
    g_sp_cnt = 0u;
}

// ---------------- Kernel A: EOP insertion (1 block per batch row) ------------
// 1024 threads, 8 elements/thread over S=8192.
__global__ __launch_bounds__(1024)
void eop_kernel(const int* __restrict__ seq,
                const int* __restrict__ end_mask,   // bool materialized as int32
                const int* __restrict__ kpm,        // bool materialized as int32
                const int* __restrict__ seg,
                const int* __restrict__ eop_id_p,
                const int* __restrict__ pad_id_p,
                float* __restrict__ out,       // [B,S]
                float* __restrict__ out_kpm,   // [B,S]
                float* __restrict__ out_seg)   // [B,S]
{
    const int b    = blockIdx.x;
    const int tid  = threadIdx.x;
    const int lane = tid & 31;
    const int wid  = tid >> 5;
    const int base = b * S_;
    const int eop_id = *eop_id_p;
    const int pad_id = *pad_id_p;

    const int EPT = 8;
    const int idx0 = tid * EPT;

    int m0[8], kp[8], sg[8], sq[8];
#pragma unroll
    for (int i = 0; i < EPT; i++) {
        int j = base + idx0 + i;
        m0[i] = end_mask[j] ? 1 : 0;
        kp[i] = kpm[j]      ? 1 : 0;
        sg[i] = seg[j];
        sq[i] = seq[j];
    }

    int localM = 0, localPad = 0, localMaxSeg = -1;
#pragma unroll
    for (int i = 0; i < EPT; i++) {
        localM   += m0[i];
        localPad += kp[i];
        if (!kp[i]) localMaxSeg = max(localMaxSeg, sg[i]);
    }

    __shared__ int sh_scan[32];
    __shared__ int sh_pad[32];
    __shared__ int sh_max[32];
    __shared__ int sh_padTot;
    __shared__ int sh_lastSeg;

    // warp inclusive scan of localM
    int sc = localM;
#pragma unroll
    for (int o = 1; o < 32; o <<= 1) {
        int v = __shfl_up_sync(0xffffffffu, sc, o);
        if (lane >= o) sc += v;
    }
    // warp reductions for pad count and max seg
    int p = localPad, mx = localMaxSeg;
#pragma unroll
    for (int o = 16; o > 0; o >>= 1) {
        p  += __shfl_down_sync(0xffffffffu, p,  o);
        mx  = max(mx, __shfl_down_sync(0xffffffffu, mx, o));
    }
    if (lane == 31) sh_scan[wid] = sc;
    if (lane == 0) { sh_pad[wid] = p; sh_max[wid] = mx; }
    __syncthreads();

    if (wid == 0) {
        int v = sh_scan[lane];
        int s2 = v;
#pragma unroll
        for (int o = 1; o < 32; o <<= 1) {
            int u = __shfl_up_sync(0xffffffffu, s2, o);
            if (lane >= o) s2 += u;
        }
        sh_scan[lane] = s2;
        int pp = sh_pad[lane], mm = sh_max[lane];
#pragma unroll
        for (int o = 16; o > 0; o >>= 1) {
            pp += __shfl_down_sync(0xffffffffu, pp, o);
            mm  = max(mm, __shfl_down_sync(0xffffffffu, mm, o));
        }
        if (lane == 0) { sh_padTot = pp; sh_lastSeg = max(mm, 0); }
    }
    __syncthreads();

    const int warpPrefix = (wid > 0) ? sh_scan[wid - 1] : 0;
    const int myExcl     = warpPrefix + sc - localM;   // exclusive prefix of end_mask
    const int pad_slots  = sh_padTot;
    const int last_seg   = sh_lastSeg;

    // init outputs (every slot gets defaults; pads keep them)
#pragma unroll
    for (int i = 0; i < EPT; i++) {
        int j = base + idx0 + i;
        out[j]     = (float)pad_id;
        out_kpm[j] = 1.0f;
        out_seg[j] = (float)last_seg;
    }
    __syncthreads();

    // scatter (destinations are provably disjoint -> no atomics)
    int csum = myExcl;
#pragma unroll
    for (int i = 0; i < EPT; i++) {
        csum += m0[i];                              // inclusive cumsum of raw end_mask
        int cc    = min(csum, pad_slots);           // capped inclusive cumsum
        int m     = (m0[i] && csum <= pad_slots) ? 1 : 0;
        int shift = cc - m;                         // exclusive capped cumsum
        if (!kp[i]) {
            int t = idx0 + i + shift;
            if (t < S_) {
                out[base + t]     = (float)sq[i];
                out_kpm[base + t] = 0.0f;
                out_seg[base + t] = (float)sg[i];
            }
            if (m && (t + 1) < S_) {
                out[base + t + 1]     = (float)eop_id;
                out_kpm[base + t + 1] = 0.0f;
                out_seg[base + t + 1] = (float)sg[i];
            }
        }
    }
}

// ---------------- Kernel B: digit CE (one warp per 512-wide row) -------------
__global__ __launch_bounds__(256)
void ce_kernel(const float* __restrict__ stage_logits,  // (2,B,S,512)
               const int* __restrict__ targets,         // (B,S)
               const int* __restrict__ tgt_kpm)         // bool as int32
{
    const int lane = threadIdx.x & 31;
    const int wib  = threadIdx.x >> 5;                   // warp in block (0..7)
    const int wg   = blockIdx.x * 8 + wib;               // global row id [0, 131072)
    const int r    = wg & (BS_ - 1);
    const int s    = wg >> 16;                            // stage

    __shared__ double sh_ce[8];
    __shared__ int    sh_cnt[8];

    double ce  = 0.0;
    int    cnt = 0;

    const int tgt = targets[r];
    const bool valid = (tgt < BASE_) && (tgt_kpm[r] == 0);

    if (valid) {
        const float4* row = (const float4*)(stage_logits + (size_t)wg * K_);
        float4 a = __ldg(row + lane);
        float4 b = __ldg(row + lane + 32);
        float4 c = __ldg(row + lane + 64);
        float4 d = __ldg(row + lane + 96);

        float mx = fmaxf(fmaxf(fmaxf(a.x, a.y), fmaxf(a.z, a.w)),
                   fmaxf(fmaxf(fmaxf(b.x, b.y), fmaxf(b.z, b.w)),
                   fmaxf(fmaxf(fmaxf(c.x, c.y), fmaxf(c.z, c.w)),
                         fmaxf(fmaxf(d.x, d.y), fmaxf(d.z, d.w)))));
#pragma unroll
        for (int o = 16; o > 0; o >>= 1)
            mx = fmaxf(mx, __shfl_xor_sync(0xffffffffu, mx, o));

        float sum = __expf(a.x - mx) + __expf(a.y - mx) + __expf(a.z - mx) + __expf(a.w - mx)
                  + __expf(b.x - mx) + __expf(b.y - mx) + __expf(b.z - mx) + __expf(b.w - mx)
                  + __expf(c.x - mx) + __expf(c.y - mx) + __expf(c.z - mx) + __expf(c.w - mx)
                  + __expf(d.x - mx) + __expf(d.y - mx) + __expf(d.z - mx) + __expf(d.w - mx);
#pragma unroll
        for (int o = 16; o > 0; o >>= 1)
            sum += __shfl_xor_sync(0xffffffffu, sum, o);

        if (lane == 0) {
            int dig = (s == 0) ? (tgt & (K_ - 1)) : ((tgt >> 9) & (K_ - 1));
            float xt = __ldg(stage_logits + (size_t)wg * K_ + dig);
            ce  = (double)(logf(sum) + mx - xt);
            cnt = (s == 0) ? 1 : 0;   // count denom once (same across stages)
        }
    }

    if (lane == 0) { sh_ce[wib] = ce; sh_cnt[wib] = cnt; }
    __syncthreads();
    if (threadIdx.x == 0) {
        double tot = 0.0; int c = 0;
#pragma unroll
        for (int i = 0; i < 8; i++) { tot += sh_ce[i]; c += sh_cnt[i]; }
        if (tot != 0.0) atomicAdd(&g_ce_sum, tot);
        if (c) atomicAdd(&g_valid_cnt, (unsigned int)c);
    }
}

// ---------------- Kernel C: special-head CE (tiny) ----------------------------
__global__ __launch_bounds__(256)
void special_kernel(const float* __restrict__ sp_logits,  // (B,S,4)
                    const int* __restrict__ targets,
                    const int* __restrict__ tgt_kpm)      // bool as int32
{
    const int i = blockIdx.x * blockDim.x + threadIdx.x;
    double ce = 0.0; int c = 0;
    if (i < BS_) {
        int t = targets[i];
        if (t >= BASE_ && tgt_kpm[i] == 0) {
            const float* p = sp_logits + (size_t)i * 4;
            float a = p[0], b = p[1], cc = p[2], d = p[3];
            float mx  = fmaxf(fmaxf(a, b), fmaxf(cc, d));
            float sum = __expf(a - mx) + __expf(b - mx) + __expf(cc - mx) + __expf(d - mx);
            int loc = t - BASE_; if (loc > 3) loc = 3;
            ce = (double)(logf(sum) + mx - p[loc]);
            c  = 1;
        }
    }
    // block reduce (rare nonzeros; cheap shared pass)
    __shared__ double shd[256];
    __shared__ int    shc[256];
    shd[threadIdx.x] = ce; shc[threadIdx.x] = c;
    __syncthreads();
    for (int o = 128; o > 0; o >>= 1) {
        if (threadIdx.x < o) {
            shd[threadIdx.x] += shd[threadIdx.x + o];
            shc[threadIdx.x] += shc[threadIdx.x + o];
        }
        __syncthreads();
    }
    if (threadIdx.x == 0) {
        if (shd[0] != 0.0) atomicAdd(&g_sp_sum, shd[0]);
        if (shc[0]) atomicAdd(&g_sp_cnt, (unsigned int)shc[0]);
    }
}

// ---------------- finalize ----------------------------------------------------
__global__ void finalize_kernel(float* __restrict__ out) {
    unsigned int vc = g_valid_cnt; if (vc == 0u) vc = 1u;
    unsigned int sc = g_sp_cnt;    if (sc == 0u) sc = 1u;
    out[3 * BS_ + 0] = (float)(g_ce_sum / (double)vc);
    out[3 * BS_ + 1] = (float)(g_sp_sum / (double)sc);
}

// ---------------- launcher ----------------------------------------------------
extern "C" void kernel_launch(void* const* d_in, const int* in_sizes, int n_in,
                              void* d_out, int out_size) {
    const float* stage_logits   = (const float*)d_in[0];
    const float* special_logits = (const float*)d_in[1];
    const int*   seq            = (const int*)d_in[2];
    const int*   end_mask       = (const int*)d_in[3];
    const int*   kpm            = (const int*)d_in[4];
    const int*   seg            = (const int*)d_in[5];
    const int*   targets        = (const int*)d_in[6];
    const int*   tgt_kpm        = (const int*)d_in[7];
    const int*   eop_id         = (const int*)d_in[8];
    const int*   pad_id         = (const int*)d_in[9];

    float* out     = (float*)d_out;            // [0, BS)   : out tokens
    float* out_kpm = out + BS_;                // [BS, 2BS) : out_kpm
    float* out_seg = out + 2 * BS_;            // [2BS,3BS) : out_seg
    // [3BS] digit_ce, [3BS+1] special_ce

    init_accum_kernel<<<1, 1>>>();
    eop_kernel<<<B_, 1024>>>(seq, end_mask, kpm, seg, eop_id, pad_id,
                             out, out_kpm, out_seg);
    ce_kernel<<<NROWS_ / 8, 256>>>(stage_logits, targets, tgt_kpm);
    special_kernel<<<BS_ / 256, 256>>>(special_logits, targets, tgt_kpm);
    finalize_kernel<<<1, 1>>>(out);
}

// round 3
// speedup vs baseline: 1.3011x; 1.3011x over previous
#include <cuda_runtime.h>
#include <cuda_bf16.h>
#include <math.h>

// Problem constants (fixed by the dataset)
#define B_      8
#define S_      8192
#define K_      512
#define BS_     65536          // B*S
#define BASE_   262144         // K^2
#define NSLOT_  64
#define EOP_BLOCKS_ 8
#define CE_BLOCKS_  (BS_ / 8)  // 8192 (8 warps/block, 1 token/warp)

// ---- partial accumulators (load-time zeroed; finalize resets after read) ----
__device__ double g_ce_part[NSLOT_];
__device__ double g_sp_part[NSLOT_];
__device__ int    g_vc_part[NSLOT_];
__device__ int    g_sc_part[NSLOT_];

__device__ __forceinline__ float pick512(float4 a, float4 b, float4 c, float4 d,
                                         int dig) {
    // dig is warp-uniform. element layout per lane L:
    // a: [4L,4L+3], b: 128+4L.., c: 256+.., d: 384+..
    int chunk = dig >> 7;          // which of a/b/c/d
    int owner = (dig >> 2) & 31;   // lane holding it
    int sub   = dig & 3;
    float4 q = (chunk == 0) ? a : (chunk == 1) ? b : (chunk == 2) ? c : d;
    float v  = (sub == 0) ? q.x : (sub == 1) ? q.y : (sub == 2) ? q.z : q.w;
    return __shfl_sync(0xffffffffu, v, owner);
}

__device__ __forceinline__ float max4(float4 v) {
    return fmaxf(fmaxf(v.x, v.y), fmaxf(v.z, v.w));
}
__device__ __forceinline__ float esum4(float4 v, float mx) {
    return __expf(v.x - mx) + __expf(v.y - mx) + __expf(v.z - mx) + __expf(v.w - mx);
}

// =============================================================================
// Fused kernel: blocks [0,8) do EOP insertion (one batch row each);
// blocks [8, 8+CE_BLOCKS) do digit CE + special CE (one token per warp).
// =============================================================================
__global__ __launch_bounds__(256)
void fused_kernel(const float* __restrict__ stage_logits,   // (2,B,S,512)
                  const float* __restrict__ special_logits, // (B,S,4)
                  const int* __restrict__ seq,
                  const int* __restrict__ end_mask,  // bool as int32
                  const int* __restrict__ kpm,       // bool as int32
                  const int* __restrict__ seg,
                  const int* __restrict__ targets,
                  const int* __restrict__ tgt_kpm,   // bool as int32
                  const int* __restrict__ eop_id_p,
                  const int* __restrict__ pad_id_p,
                  float* __restrict__ out,
                  float* __restrict__ out_kpm,
                  float* __restrict__ out_seg)
{
    const int tid  = threadIdx.x;
    const int lane = tid & 31;
    const int wib  = tid >> 5;

    if (blockIdx.x < EOP_BLOCKS_) {
        // ------------------------- EOP insertion path -----------------------
        const int b    = blockIdx.x;
        const int base = b * S_;
        const int idx0 = tid * 32;          // 256 threads * 32 = 8192

        unsigned mbits = 0u, kbits = 0u;
        int localM = 0, localPad = 0, localMax = -1;
#pragma unroll 4
        for (int i = 0; i < 32; i++) {
            int j = base + idx0 + i;
            int m = end_mask[j] ? 1 : 0;
            int k = kpm[j] ? 1 : 0;
            mbits |= (unsigned)m << i;
            kbits |= (unsigned)k << i;
            localM += m;
            localPad += k;
            if (!k) localMax = max(localMax, seg[j]);
        }

        __shared__ int s_sum[8], s_pad[8], s_max[8];
        __shared__ int s_excl[8];
        __shared__ int s_padTot, s_lastSeg;

        // warp inclusive scan of localM; warp reduce pad/max
        int sc = localM;
#pragma unroll
        for (int o = 1; o < 32; o <<= 1) {
            int v = __shfl_up_sync(0xffffffffu, sc, o);
            if (lane >= o) sc += v;
        }
        int p = localPad, mx = localMax;
#pragma unroll
        for (int o = 16; o > 0; o >>= 1) {
            p  += __shfl_down_sync(0xffffffffu, p, o);
            mx  = max(mx, __shfl_down_sync(0xffffffffu, mx, o));
        }
        if (lane == 31) s_sum[wib] = sc;
        if (lane == 0) { s_pad[wib] = p; s_max[wib] = mx; }
        __syncthreads();
        if (tid == 0) {
            int acc = 0, pt = 0, mm = -1;
#pragma unroll
            for (int i = 0; i < 8; i++) {
                s_excl[i] = acc;
                acc += s_sum[i];
                pt  += s_pad[i];
                mm   = max(mm, s_max[i]);
            }
            s_padTot  = pt;
            s_lastSeg = max(mm, 0);
        }
        __syncthreads();

        const int myExcl    = s_excl[wib] + sc - localM;  // exclusive end_mask prefix
        const int pad_slots = s_padTot;
        const float lastSegF = (float)s_lastSeg;
        const int eop_id = *eop_id_p;
        const int pad_id = *pad_id_p;
        const float padF = (float)pad_id;
        const float eopF = (float)eop_id;

        // defaults
#pragma unroll 4
        for (int i = 0; i < 32; i++) {
            int j = base + idx0 + i;
            out[j]     = padF;
            out_kpm[j] = 1.0f;
            out_seg[j] = lastSegF;
        }
        __syncthreads();

        // scatter (destinations disjoint — no atomics)
        int csum = myExcl;
#pragma unroll 4
        for (int i = 0; i < 32; i++) {
            int m0 = (mbits >> i) & 1;
            csum += m0;
            int cc    = min(csum, pad_slots);
            int m     = (m0 && csum <= pad_slots) ? 1 : 0;
            int shift = cc - m;
            if (!((kbits >> i) & 1)) {
                int pos = idx0 + i;
                int t   = pos + shift;
                int j   = base + pos;
                float sgv = (float)seg[j];   // L1 hit (read in pass 1)
                float sqv = (float)seq[j];
                if (t < S_) {
                    out[base + t]     = sqv;
                    out_kpm[base + t] = 0.0f;
                    out_seg[base + t] = sgv;
                }
                if (m && (t + 1) < S_) {
                    out[base + t + 1]     = eopF;
                    out_kpm[base + t + 1] = 0.0f;
                    out_seg[base + t + 1] = sgv;
                }
            }
        }
        return;
    }

    // ----------------------------- CE path ----------------------------------
    const int token = (blockIdx.x - EOP_BLOCKS_) * 8 + wib;   // [0, BS_)
    const int tgt  = targets[token];   // warp-uniform broadcast load
    const int padf = tgt_kpm[token];

    double ce = 0.0, spce = 0.0;
    int vc = 0, scnt = 0;

    if (!padf) {
        if (tgt < BASE_) {
            const float4* r0 = (const float4*)(stage_logits + (size_t)token * K_);
            const float4* r1 = (const float4*)(stage_logits + (size_t)(BS_ + token) * K_);
            float4 a0 = __ldcs(r0 + lane),      b0 = __ldcs(r0 + lane + 32),
                   c0 = __ldcs(r0 + lane + 64), d0 = __ldcs(r0 + lane + 96);
            float4 a1 = __ldcs(r1 + lane),      b1 = __ldcs(r1 + lane + 32),
                   c1 = __ldcs(r1 + lane + 64), d1 = __ldcs(r1 + lane + 96);

            float m0 = fmaxf(fmaxf(max4(a0), max4(b0)), fmaxf(max4(c0), max4(d0)));
            float m1 = fmaxf(fmaxf(max4(a1), max4(b1)), fmaxf(max4(c1), max4(d1)));
#pragma unroll
            for (int o = 16; o > 0; o >>= 1) {
                m0 = fmaxf(m0, __shfl_xor_sync(0xffffffffu, m0, o));
                m1 = fmaxf(m1, __shfl_xor_sync(0xffffffffu, m1, o));
            }
            float s0 = esum4(a0, m0) + esum4(b0, m0) + esum4(c0, m0) + esum4(d0, m0);
            float s1 = esum4(a1, m1) + esum4(b1, m1) + esum4(c1, m1) + esum4(d1, m1);
#pragma unroll
            for (int o = 16; o > 0; o >>= 1) {
                s0 += __shfl_xor_sync(0xffffffffu, s0, o);
                s1 += __shfl_xor_sync(0xffffffffu, s1, o);
            }
            int dig0 = tgt & (K_ - 1);
            int dig1 = (tgt >> 9) & (K_ - 1);
            float x0 = pick512(a0, b0, c0, d0, dig0);
            float x1 = pick512(a1, b1, c1, d1, dig1);
            if (lane == 0) {
                ce = (double)((__logf(s0) + m0 - x0) + (__logf(s1) + m1 - x1));
                vc = 1;
            }
        } else {
            if (lane == 0) {
                float4 pv = *(const float4*)(special_logits + (size_t)token * 4);
                float mxs  = fmaxf(fmaxf(pv.x, pv.y), fmaxf(pv.z, pv.w));
                float sums = __expf(pv.x - mxs) + __expf(pv.y - mxs)
                           + __expf(pv.z - mxs) + __expf(pv.w - mxs);
                int loc = tgt - BASE_;
                if (loc > 3) loc = 3;
                float xt = (loc == 0) ? pv.x : (loc == 1) ? pv.y : (loc == 2) ? pv.z : pv.w;
                spce = (double)(__logf(sums) + mxs - xt);
                scnt = 1;
            }
        }
    }

    __shared__ double sh_ce[8], sh_sp[8];
    __shared__ int sh_vc[8], sh_sc[8];
    if (lane == 0) { sh_ce[wib] = ce; sh_sp[wib] = spce; sh_vc[wib] = vc; sh_sc[wib] = scnt; }
    __syncthreads();
    if (tid == 0) {
        double tc = 0.0, ts = 0.0;
        int cv = 0, cs = 0;
#pragma unroll
        for (int i = 0; i < 8; i++) {
            tc += sh_ce[i]; ts += sh_sp[i]; cv += sh_vc[i]; cs += sh_sc[i];
        }
        int slot = blockIdx.x & (NSLOT_ - 1);
        if (tc != 0.0) atomicAdd(&g_ce_part[slot], tc);
        if (cv)        atomicAdd(&g_vc_part[slot], cv);
        if (ts != 0.0) atomicAdd(&g_sp_part[slot], ts);
        if (cs)        atomicAdd(&g_sc_part[slot], cs);
    }
}

// ---------------- finalize: reduce 64 slots, write scalars, reset ------------
__global__ void finalize_kernel(float* __restrict__ out) {
    const int t = threadIdx.x;   // 64 threads
    double ce = g_ce_part[t], sp = g_sp_part[t];
    int vc = g_vc_part[t], sc = g_sc_part[t];
    g_ce_part[t] = 0.0; g_sp_part[t] = 0.0;
    g_vc_part[t] = 0;   g_sc_part[t] = 0;

    __shared__ double sd[64], ss[64];
    __shared__ int sv[64], sn[64];
    sd[t] = ce; ss[t] = sp; sv[t] = vc; sn[t] = sc;
    __syncthreads();
    if (t == 0) {
        double a = 0.0, b = 0.0;
        int v = 0, n = 0;
#pragma unroll
        for (int i = 0; i < 64; i++) { a += sd[i]; b += ss[i]; v += sv[i]; n += sn[i]; }
        if (v == 0) v = 1;
        if (n == 0) n = 1;
        out[3 * BS_ + 0] = (float)(a / (double)v);
        out[3 * BS_ + 1] = (float)(b / (double)n);
    }
}

// ---------------- launcher ----------------------------------------------------
extern "C" void kernel_launch(void* const* d_in, const int* in_sizes, int n_in,
                              void* d_out, int out_size) {
    const float* stage_logits   = (const float*)d_in[0];
    const float* special_logits = (const float*)d_in[1];
    const int*   seq            = (const int*)d_in[2];
    const int*   end_mask       = (const int*)d_in[3];
    const int*   kpm            = (const int*)d_in[4];
    const int*   seg            = (const int*)d_in[5];
    const int*   targets        = (const int*)d_in[6];
    const int*   tgt_kpm        = (const int*)d_in[7];
    const int*   eop_id         = (const int*)d_in[8];
    const int*   pad_id         = (const int*)d_in[9];

    float* out     = (float*)d_out;            // [0, BS)   : tokens
    float* out_kpm = out + BS_;                // [BS, 2BS)
    float* out_seg = out + 2 * BS_;            // [2BS,3BS)
    // [3BS] digit_ce, [3BS+1] special_ce

    fused_kernel<<<EOP_BLOCKS_ + CE_BLOCKS_, 256>>>(
        stage_logits, special_logits, seq, end_mask, kpm, seg,
        targets, tgt_kpm, eop_id, pad_id, out, out_kpm, out_seg);
    finalize_kernel<<<1, 64>>>(out);
}